// round 14
// baseline (speedup 1.0000x reference)
#include <cuda_runtime.h>
#include <cuda_fp16.h>
#include <cstdint>

#define TOK   8192
#define HDIM  1024
#define FDIM  4096
#define NE    8

// ---------------- scratch (static device globals) ---------------------------
// g_counts is zero-initialized at module load; scan_kernel re-zeroes it after
// use, so "counts == 0 at router entry" holds on every sequential execution.
__device__ int    g_counts[NE];
__device__ int    g_offsets[NE + 1];
__device__ int    g_cursor[NE];
__device__ int    g_topk_i[TOK * 2];
__device__ float  g_topk_w[TOK * 2];
__device__ int    g_list[TOK * 2];
__device__ __half g_xh[(size_t)TOK * HDIM];            // x in fp16
__device__ __half g_w1h[(size_t)NE * HDIM * FDIM];     // w1 in fp16
__device__ __half g_w2h[(size_t)NE * FDIM * HDIM];     // w2 in fp16
__device__ __half g_hidh[(size_t)TOK * 2 * FDIM];      // gelu(x@w1+b1) fp16

// ---------------- PTX helpers ------------------------------------------------
__device__ __forceinline__ uint32_t smem_u32(const void* p) {
    uint32_t a;
    asm("{ .reg .u64 t; cvta.to.shared.u64 t, %1; cvt.u32.u64 %0, t; }" : "=r"(a) : "l"(p));
    return a;
}
__device__ __forceinline__ void cp16(uint32_t dst, const void* src, int bytes) {
    asm volatile("cp.async.cg.shared.global [%0], [%1], 16, %2;"
                 :: "r"(dst), "l"(src), "r"(bytes));
}
__device__ __forceinline__ void ldsm4(uint32_t* r, uint32_t addr) {
    asm volatile("ldmatrix.sync.aligned.m8n8.x4.shared.b16 {%0,%1,%2,%3}, [%4];"
                 : "=r"(r[0]), "=r"(r[1]), "=r"(r[2]), "=r"(r[3]) : "r"(addr));
}
__device__ __forceinline__ void ldsm4t(uint32_t* r, uint32_t addr) {
    asm volatile("ldmatrix.sync.aligned.m8n8.x4.trans.shared.b16 {%0,%1,%2,%3}, [%4];"
                 : "=r"(r[0]), "=r"(r[1]), "=r"(r[2]), "=r"(r[3]) : "r"(addr));
}
__device__ __forceinline__ void mma_f16(float* d, const uint32_t* a, const uint32_t* b) {
    asm volatile(
        "mma.sync.aligned.m16n8k16.row.col.f32.f16.f16.f32 "
        "{%0,%1,%2,%3}, {%4,%5,%6,%7}, {%8,%9}, {%0,%1,%2,%3};"
        : "+f"(d[0]), "+f"(d[1]), "+f"(d[2]), "+f"(d[3])
        : "r"(a[0]), "r"(a[1]), "r"(a[2]), "r"(a[3]), "r"(b[0]), "r"(b[1]));
}
__device__ __forceinline__ float gelu_exact(float v) {
    return 0.5f * v * (1.0f + erff(v * 0.70710678118654752f));
}

// ---------------- small kernels ----------------------------------------------
__global__ void zero_out_kernel(float* __restrict__ out, size_t n4) {
    size_t i = (size_t)blockIdx.x * blockDim.x + threadIdx.x;
    if (i < n4) ((float4*)out)[i] = make_float4(0.f, 0.f, 0.f, 0.f);
}

__global__ void cvt_half_kernel(const float* __restrict__ src, __half* __restrict__ dst,
                                size_t n8) {
    size_t i = (size_t)blockIdx.x * blockDim.x + threadIdx.x;
    if (i < n8) {
        float4 v0 = ((const float4*)src)[i * 2];
        float4 v1 = ((const float4*)src)[i * 2 + 1];
        __half2 h[4];
        h[0] = __floats2half2_rn(v0.x, v0.y);
        h[1] = __floats2half2_rn(v0.z, v0.w);
        h[2] = __floats2half2_rn(v1.x, v1.y);
        h[3] = __floats2half2_rn(v1.z, v1.w);
        ((uint4*)dst)[i] = *(uint4*)h;
    }
}

__global__ void router_kernel(const float* __restrict__ x, const float* __restrict__ rw) {
    __shared__ float srw[NE * HDIM];
    int tid = threadIdx.x;
    for (int i = tid; i < NE * HDIM; i += 256) srw[i] = rw[i];
    __syncthreads();
    int warp = tid >> 5, lane = tid & 31;
    int t = blockIdx.x * 8 + warp;
    if (t >= TOK) return;
    const float* xr = x + (size_t)t * HDIM;
    float acc[NE];
#pragma unroll
    for (int e = 0; e < NE; e++) acc[e] = 0.0f;
    for (int h = lane; h < HDIM; h += 32) {
        float xv = xr[h];
#pragma unroll
        for (int e = 0; e < NE; e++) acc[e] += xv * srw[e * HDIM + h];
    }
#pragma unroll
    for (int off = 16; off > 0; off >>= 1)
#pragma unroll
        for (int e = 0; e < NE; e++) acc[e] += __shfl_xor_sync(0xffffffffu, acc[e], off);
    if (lane == 0) {
        float mx = acc[0];
#pragma unroll
        for (int e = 1; e < NE; e++) mx = fmaxf(mx, acc[e]);
        float p[NE], s = 0.0f;
#pragma unroll
        for (int e = 0; e < NE; e++) { p[e] = expf(acc[e] - mx); s += p[e]; }
        float inv = 1.0f / s;
#pragma unroll
        for (int e = 0; e < NE; e++) p[e] *= inv;
        int i1 = 0;
#pragma unroll
        for (int e = 1; e < NE; e++) if (p[e] > p[i1]) i1 = e;
        int i2 = (i1 == 0) ? 1 : 0;
#pragma unroll
        for (int e = 0; e < NE; e++) if (e != i1 && p[e] > p[i2]) i2 = e;
        g_topk_i[t * 2 + 0] = i1; g_topk_w[t * 2 + 0] = p[i1];
        g_topk_i[t * 2 + 1] = i2; g_topk_w[t * 2 + 1] = p[i2];
        atomicAdd(&g_counts[i1], 1);
        atomicAdd(&g_counts[i2], 1);
    }
}

// scan + reset counts for the next invocation (counts no longer needed after)
__global__ void scan_kernel() {
    if (threadIdx.x == 0) {
        int o = 0;
        g_offsets[0] = 0;
        for (int e = 0; e < NE; e++) {
            g_cursor[e] = o;
            o += g_counts[e];
            g_offsets[e + 1] = o;
            g_counts[e] = 0;            // re-arm for next call/replay
        }
    }
}

__global__ void scatter_kernel() {
    int t = blockIdx.x * 256 + threadIdx.x;
    if (t < TOK) {
#pragma unroll
        for (int s = 0; s < 2; s++) {
            int e = g_topk_i[t * 2 + s];
            int pos = atomicAdd(&g_cursor[e], 1);
            g_list[pos] = t * 2 + s;
        }
    }
}

// ---------------- fp16 grouped GEMM (m16n8k16 + ldmatrix) --------------------
// Tile 128x128, BK=64, 128 threads = 4 warps (2Mx2N), warp tile 64x64.
// 3-stage cp.async pipeline, one __syncthreads per K-tile. (R4 hot loop.)
// Covers a 4-expert group starting at e0 (blockIdx.y: 4 experts x 64 rowtiles).
template <int KD, int ND, bool FFN1>
__global__ void __launch_bounds__(128, 2)
moe_gemm_h(const __half* __restrict__ Ah, const __half* __restrict__ Wh,
           const float* __restrict__ bias, float* __restrict__ outp, int e0) {
    extern __shared__ char smem[];
    uint32_t smb = smem_u32(smem);

    int tid = threadIdx.x;
    int warp = tid >> 5, lane = tid & 31;
    int wm = warp & 1, wn = warp >> 1;
    int l15 = lane & 15, hi = lane >> 4;

    int e = e0 + (blockIdx.y >> 6);
    int rt = blockIdx.y & 63;
    int seg0 = g_offsets[e], seg1 = g_offsets[e + 1];
    int row0 = seg0 + rt * 128;
    if (row0 >= seg1) return;
    int n0 = blockIdx.x * 128;

    // ---- A loader: 8 chunks/thread ----
    const __half* a_src[8];
    int a_bytes[8];
#pragma unroll
    for (int j = 0; j < 8; j++) {
        int idx = tid + 128 * j;
        int row = idx >> 3, c = idx & 7;
        int grow = row0 + row;
        bool v = grow < seg1;
        if (FFN1) {
            int pair = v ? g_list[grow] : 0;
            a_src[j] = Ah + (size_t)(pair >> 1) * KD + c * 8;
        } else {
            a_src[j] = Ah + (size_t)(v ? grow : row0) * KD + c * 8;
        }
        a_bytes[j] = v ? 16 : 0;
    }
    const __half* wbase = Wh + (size_t)e * KD * ND + n0;

    auto load_stage = [&](int s, int kt) {
        int k0 = kt * 64;
        uint32_t base = smb + s * 32768;
#pragma unroll
        for (int j = 0; j < 8; j++) {
            int idx = tid + 128 * j;
            int row = idx >> 3, c = idx & 7;
            uint32_t off = (uint32_t)row * 128 + (uint32_t)((c ^ (row & 7)) << 4);
            cp16(base + off, a_src[j] + k0, a_bytes[j]);
        }
#pragma unroll
        for (int j = 0; j < 8; j++) {
            int idx = tid + 128 * j;
            int k = idx >> 4, c = idx & 15;
            uint32_t off = 16384u + (uint32_t)k * 256 + (uint32_t)((c ^ (k & 7)) << 4);
            cp16(base + off, wbase + (size_t)(k0 + k) * ND + c * 8, 16);
        }
        asm volatile("cp.async.commit_group;");
    };

    float acc[4][8][4];
#pragma unroll
    for (int mi = 0; mi < 4; mi++)
#pragma unroll
        for (int ni = 0; ni < 8; ni++)
#pragma unroll
            for (int d = 0; d < 4; d++) acc[mi][ni][d] = 0.0f;

    constexpr int KT = KD / 64;
    load_stage(0, 0);
    load_stage(1, 1);

    for (int kt = 0; kt < KT; kt++) {
        if (kt + 1 < KT) asm volatile("cp.async.wait_group 1;");
        else             asm volatile("cp.async.wait_group 0;");
        __syncthreads();
        if (kt + 2 < KT) load_stage((kt + 2) % 3, kt + 2);

        uint32_t abase = smb + (kt % 3) * 32768;
        uint32_t bbase = abase + 16384;
#pragma unroll
        for (int ks = 0; ks < 4; ks++) {
            uint32_t a[4][4];
#pragma unroll
            for (int mi = 0; mi < 4; mi++) {
                int row = wm * 64 + mi * 16 + l15;
                uint32_t addr = abase + (uint32_t)row * 128 +
                                (uint32_t)(((ks * 2 + hi) ^ (row & 7)) << 4);
                ldsm4(a[mi], addr);
            }
            uint32_t b[4][4];
#pragma unroll
            for (int np = 0; np < 4; np++) {
                int krow = ks * 16 + l15;
                int c = wn * 8 + np * 2 + hi;
                uint32_t addr = bbase + (uint32_t)krow * 256 +
                                (uint32_t)((c ^ (krow & 7)) << 4);
                ldsm4t(b[np], addr);
            }
#pragma unroll
            for (int mi = 0; mi < 4; mi++)
#pragma unroll
                for (int np = 0; np < 4; np++) {
                    mma_f16(acc[mi][np * 2 + 0], a[mi], b[np] + 0);
                    mma_f16(acc[mi][np * 2 + 1], a[mi], b[np] + 2);
                }
        }
    }

    // ---- epilogue ----
    int r4 = lane >> 2, c2 = (lane & 3) * 2;
#pragma unroll
    for (int mi = 0; mi < 4; mi++) {
#pragma unroll
        for (int h = 0; h < 2; h++) {
            int grow = row0 + wm * 64 + mi * 16 + r4 + h * 8;
            if (grow < seg1) {
                if (FFN1) {
                    __half* orow = g_hidh + (size_t)grow * ND;
#pragma unroll
                    for (int ni = 0; ni < 8; ni++) {
                        int col = n0 + wn * 64 + ni * 8 + c2;
                        float2 bv = *(const float2*)(bias + (size_t)e * ND + col);
                        float v0 = gelu_exact(acc[mi][ni][h * 2 + 0] + bv.x);
                        float v1 = gelu_exact(acc[mi][ni][h * 2 + 1] + bv.y);
                        *(__half2*)(orow + col) = __floats2half2_rn(v0, v1);
                    }
                } else {
                    int pair = g_list[grow];
                    float wgt = g_topk_w[pair];
                    float* orow = outp + (size_t)(pair >> 1) * ND;
#pragma unroll
                    for (int ni = 0; ni < 8; ni++) {
                        int col = n0 + wn * 64 + ni * 8 + c2;
                        float2 bv = *(const float2*)(bias + (size_t)e * ND + col);
                        float v0 = (acc[mi][ni][h * 2 + 0] + bv.x) * wgt;
                        float v1 = (acc[mi][ni][h * 2 + 1] + bv.y) * wgt;
                        atomicAdd(orow + col, v0);
                        atomicAdd(orow + col + 1, v1);
                    }
                }
            }
        }
    }
}

// ---------------- launch --------------------------------------------------------
extern "C" void kernel_launch(void* const* d_in, const int* in_sizes, int n_in,
                              void* d_out, int out_size) {
    const float* x  = (const float*)d_in[0];
    const float* rw = (const float*)d_in[1];
    const float* w1 = (const float*)d_in[2];
    const float* b1 = (const float*)d_in[3];
    const float* w2 = (const float*)d_in[4];
    const float* b2 = (const float*)d_in[5];
    float* out = (float*)d_out;

    __half* xh;  cudaGetSymbolAddress((void**)&xh,  g_xh);
    __half* w1h; cudaGetSymbolAddress((void**)&w1h, g_w1h);
    __half* w2h; cudaGetSymbolAddress((void**)&w2h, g_w2h);
    __half* hid; cudaGetSymbolAddress((void**)&hid, g_hidh);

    constexpr int SMEM_BYTES = 3 * 32768;  // 98304
    cudaFuncSetAttribute(moe_gemm_h<HDIM, FDIM, true >,
                         cudaFuncAttributeMaxDynamicSharedMemorySize, SMEM_BYTES);
    cudaFuncSetAttribute(moe_gemm_h<FDIM, HDIM, false>,
                         cudaFuncAttributeMaxDynamicSharedMemorySize, SMEM_BYTES);

    // Lazily-created side streams + events (host handles only; reused so the
    // captured work is identical on every call).
    static cudaStream_t s2 = nullptr, s3 = nullptr;
    static cudaEvent_t  ev_fork = nullptr, ev_w1 = nullptr, ev_w2 = nullptr;
    static cudaEvent_t  ev_sc = nullptr, ev_join = nullptr;
    if (s2 == nullptr) {
        cudaStreamCreateWithFlags(&s2, cudaStreamNonBlocking);
        cudaStreamCreateWithFlags(&s3, cudaStreamNonBlocking);
        cudaEventCreateWithFlags(&ev_fork, cudaEventDisableTiming);
        cudaEventCreateWithFlags(&ev_w1,   cudaEventDisableTiming);
        cudaEventCreateWithFlags(&ev_w2,   cudaEventDisableTiming);
        cudaEventCreateWithFlags(&ev_sc,   cudaEventDisableTiming);
        cudaEventCreateWithFlags(&ev_join, cudaEventDisableTiming);
    }

    size_t nx   = (size_t)TOK * HDIM / 8;
    size_t nw1  = (size_t)NE * HDIM * FDIM / 8;          // in float8 units
    size_t nw1h = nw1 / 2;                                // experts 0..3
    size_t ow1  = (size_t)4 * HDIM * FDIM;                // element offset e4
    size_t nw2  = (size_t)NE * FDIM * HDIM / 8;
    size_t no4  = (size_t)TOK * HDIM / 4;

    cudaEventRecord(ev_fork, 0);

    // ---- s2: FFN1-feeding conversions ONLY, then FFN1b/FFN2b ----
    cudaStreamWaitEvent(s2, ev_fork, 0);
    cvt_half_kernel<<<(int)((nx   + 255) / 256), 256, 0, s2>>>(x,  xh,  nx);
    cvt_half_kernel<<<(int)((nw1h + 255) / 256), 256, 0, s2>>>(w1, w1h, nw1h);
    cudaEventRecord(ev_w1, s2);
    cvt_half_kernel<<<(int)((nw1h + 255) / 256), 256, 0, s2>>>(w1 + ow1, w1h + ow1, nw1h);

    // ---- s3: FFN2-only prologue (zero out + cvt w2), off FFN1's path ----
    cudaStreamWaitEvent(s3, ev_fork, 0);
    zero_out_kernel<<<(int)((no4 + 255) / 256), 256, 0, s3>>>(out, no4);
    cvt_half_kernel<<<(int)((nw2 + 255) / 256), 256, 0, s3>>>(w2, w2h, nw2);
    cudaEventRecord(ev_w2, s3);

    // ---- main stream: router chain in parallel with conversions ----
    router_kernel<<<TOK / 8, 256>>>(x, rw);
    scan_kernel<<<1, 32>>>();
    scatter_kernel<<<TOK / 256, 256>>>();
    cudaEventRecord(ev_sc, 0);

    // ---- 2-way expert-group pipeline (R12 winner) ----
    cudaStreamWaitEvent(0, ev_w1, 0);             // xh + w1h(e0..3) for FFN1a
    moe_gemm_h<HDIM, FDIM, true ><<<dim3(FDIM / 128, 4 * 64), 128, SMEM_BYTES>>>(
        xh, w1h, b1, out, 0);
    cudaStreamWaitEvent(s2, ev_sc, 0);            // router outputs for FFN1b
    moe_gemm_h<HDIM, FDIM, true ><<<dim3(FDIM / 128, 4 * 64), 128, SMEM_BYTES, s2>>>(
        xh, w1h, b1, out, 4);

    cudaStreamWaitEvent(0, ev_w2, 0);             // w2h + zeroed out for FFN2a
    moe_gemm_h<FDIM, HDIM, false><<<dim3(HDIM / 128, 4 * 64), 128, SMEM_BYTES>>>(
        hid, w2h, b2, out, 0);
    cudaStreamWaitEvent(s2, ev_w2, 0);            // w2h + zeroed out for FFN2b
    moe_gemm_h<FDIM, HDIM, false><<<dim3(HDIM / 128, 4 * 64), 128, SMEM_BYTES, s2>>>(
        hid, w2h, b2, out, 4);

    // join side streams back to origin (s3 joins transitively via ev_w2)
    cudaEventRecord(ev_join, s2);
    cudaStreamWaitEvent(0, ev_join, 0);
}

// round 15
// speedup vs baseline: 1.0089x; 1.0089x over previous
#include <cuda_runtime.h>
#include <cuda_fp16.h>
#include <cstdint>

#define TOK   8192
#define HDIM  1024
#define FDIM  4096
#define NE    8

// ---------------- scratch (static device globals) ---------------------------
// g_counts is zero-initialized at module load; scan_kernel re-zeroes it after
// use, so "counts == 0 at router entry" holds on every sequential execution.
__device__ int    g_counts[NE];
__device__ int    g_offsets[NE + 1];
__device__ int    g_cursor[NE];
__device__ int    g_topk_i[TOK * 2];
__device__ float  g_topk_w[TOK * 2];
__device__ int    g_list[TOK * 2];
__device__ __half g_xh[(size_t)TOK * HDIM];            // x in fp16 (written by router)
__device__ __half g_w1h[(size_t)NE * HDIM * FDIM];     // w1 in fp16
__device__ __half g_w2h[(size_t)NE * FDIM * HDIM];     // w2 in fp16
__device__ __half g_hidh[(size_t)TOK * 2 * FDIM];      // gelu(x@w1+b1) fp16

// ---------------- PTX helpers ------------------------------------------------
__device__ __forceinline__ uint32_t smem_u32(const void* p) {
    uint32_t a;
    asm("{ .reg .u64 t; cvta.to.shared.u64 t, %1; cvt.u32.u64 %0, t; }" : "=r"(a) : "l"(p));
    return a;
}
__device__ __forceinline__ void cp16(uint32_t dst, const void* src, int bytes) {
    asm volatile("cp.async.cg.shared.global [%0], [%1], 16, %2;"
                 :: "r"(dst), "l"(src), "r"(bytes));
}
__device__ __forceinline__ void ldsm4(uint32_t* r, uint32_t addr) {
    asm volatile("ldmatrix.sync.aligned.m8n8.x4.shared.b16 {%0,%1,%2,%3}, [%4];"
                 : "=r"(r[0]), "=r"(r[1]), "=r"(r[2]), "=r"(r[3]) : "r"(addr));
}
__device__ __forceinline__ void ldsm4t(uint32_t* r, uint32_t addr) {
    asm volatile("ldmatrix.sync.aligned.m8n8.x4.trans.shared.b16 {%0,%1,%2,%3}, [%4];"
                 : "=r"(r[0]), "=r"(r[1]), "=r"(r[2]), "=r"(r[3]) : "r"(addr));
}
__device__ __forceinline__ void mma_f16(float* d, const uint32_t* a, const uint32_t* b) {
    asm volatile(
        "mma.sync.aligned.m16n8k16.row.col.f32.f16.f16.f32 "
        "{%0,%1,%2,%3}, {%4,%5,%6,%7}, {%8,%9}, {%0,%1,%2,%3};"
        : "+f"(d[0]), "+f"(d[1]), "+f"(d[2]), "+f"(d[3])
        : "r"(a[0]), "r"(a[1]), "r"(a[2]), "r"(a[3]), "r"(b[0]), "r"(b[1]));
}
__device__ __forceinline__ float gelu_exact(float v) {
    return 0.5f * v * (1.0f + erff(v * 0.70710678118654752f));
}

// ---------------- small kernels ----------------------------------------------
__global__ void zero_out_kernel(float* __restrict__ out, size_t n4) {
    size_t i = (size_t)blockIdx.x * blockDim.x + threadIdx.x;
    if (i < n4) ((float4*)out)[i] = make_float4(0.f, 0.f, 0.f, 0.f);
}

__global__ void cvt_half_kernel(const float* __restrict__ src, __half* __restrict__ dst,
                                size_t n8) {
    size_t i = (size_t)blockIdx.x * blockDim.x + threadIdx.x;
    if (i < n8) {
        float4 v0 = ((const float4*)src)[i * 2];
        float4 v1 = ((const float4*)src)[i * 2 + 1];
        __half2 h[4];
        h[0] = __floats2half2_rn(v0.x, v0.y);
        h[1] = __floats2half2_rn(v0.z, v0.w);
        h[2] = __floats2half2_rn(v1.x, v1.y);
        h[3] = __floats2half2_rn(v1.z, v1.w);
        ((uint4*)dst)[i] = *(uint4*)h;
    }
}

// router + fused x -> fp16 conversion (x is streamed through here anyway)
__global__ void router_kernel(const float* __restrict__ x, const float* __restrict__ rw) {
    __shared__ float srw[NE * HDIM];
    int tid = threadIdx.x;
    for (int i = tid; i < NE * HDIM; i += 256) srw[i] = rw[i];
    __syncthreads();
    int warp = tid >> 5, lane = tid & 31;
    int t = blockIdx.x * 8 + warp;
    if (t >= TOK) return;
    const float* xr = x + (size_t)t * HDIM;
    __half* xhr = g_xh + (size_t)t * HDIM;
    float acc[NE];
#pragma unroll
    for (int e = 0; e < NE; e++) acc[e] = 0.0f;
    for (int h = lane; h < HDIM; h += 32) {
        float xv = xr[h];
        xhr[h] = __float2half_rn(xv);          // fused conversion (coalesced)
#pragma unroll
        for (int e = 0; e < NE; e++) acc[e] += xv * srw[e * HDIM + h];
    }
#pragma unroll
    for (int off = 16; off > 0; off >>= 1)
#pragma unroll
        for (int e = 0; e < NE; e++) acc[e] += __shfl_xor_sync(0xffffffffu, acc[e], off);
    if (lane == 0) {
        float mx = acc[0];
#pragma unroll
        for (int e = 1; e < NE; e++) mx = fmaxf(mx, acc[e]);
        float p[NE], s = 0.0f;
#pragma unroll
        for (int e = 0; e < NE; e++) { p[e] = expf(acc[e] - mx); s += p[e]; }
        float inv = 1.0f / s;
#pragma unroll
        for (int e = 0; e < NE; e++) p[e] *= inv;
        int i1 = 0;
#pragma unroll
        for (int e = 1; e < NE; e++) if (p[e] > p[i1]) i1 = e;
        int i2 = (i1 == 0) ? 1 : 0;
#pragma unroll
        for (int e = 0; e < NE; e++) if (e != i1 && p[e] > p[i2]) i2 = e;
        g_topk_i[t * 2 + 0] = i1; g_topk_w[t * 2 + 0] = p[i1];
        g_topk_i[t * 2 + 1] = i2; g_topk_w[t * 2 + 1] = p[i2];
        atomicAdd(&g_counts[i1], 1);
        atomicAdd(&g_counts[i2], 1);
    }
}

// scan + reset counts for the next invocation (counts no longer needed after)
__global__ void scan_kernel() {
    if (threadIdx.x == 0) {
        int o = 0;
        g_offsets[0] = 0;
        for (int e = 0; e < NE; e++) {
            g_cursor[e] = o;
            o += g_counts[e];
            g_offsets[e + 1] = o;
            g_counts[e] = 0;            // re-arm for next call/replay
        }
    }
}

__global__ void scatter_kernel() {
    int t = blockIdx.x * 256 + threadIdx.x;
    if (t < TOK) {
#pragma unroll
        for (int s = 0; s < 2; s++) {
            int e = g_topk_i[t * 2 + s];
            int pos = atomicAdd(&g_cursor[e], 1);
            g_list[pos] = t * 2 + s;
        }
    }
}

// ---------------- fp16 grouped GEMM (m16n8k16 + ldmatrix) --------------------
// Tile 128x128, BK=64, 128 threads = 4 warps (2Mx2N), warp tile 64x64.
// 3-stage cp.async pipeline, one __syncthreads per K-tile. (R4 hot loop.)
// Covers a 4-expert group starting at e0 (blockIdx.y: 4 experts x 64 rowtiles).
template <int KD, int ND, bool FFN1>
__global__ void __launch_bounds__(128, 2)
moe_gemm_h(const __half* __restrict__ Ah, const __half* __restrict__ Wh,
           const float* __restrict__ bias, float* __restrict__ outp, int e0) {
    extern __shared__ char smem[];
    uint32_t smb = smem_u32(smem);

    int tid = threadIdx.x;
    int warp = tid >> 5, lane = tid & 31;
    int wm = warp & 1, wn = warp >> 1;
    int l15 = lane & 15, hi = lane >> 4;

    int e = e0 + (blockIdx.y >> 6);
    int rt = blockIdx.y & 63;
    int seg0 = g_offsets[e], seg1 = g_offsets[e + 1];
    int row0 = seg0 + rt * 128;
    if (row0 >= seg1) return;
    int n0 = blockIdx.x * 128;

    // ---- A loader: 8 chunks/thread ----
    const __half* a_src[8];
    int a_bytes[8];
#pragma unroll
    for (int j = 0; j < 8; j++) {
        int idx = tid + 128 * j;
        int row = idx >> 3, c = idx & 7;
        int grow = row0 + row;
        bool v = grow < seg1;
        if (FFN1) {
            int pair = v ? g_list[grow] : 0;
            a_src[j] = Ah + (size_t)(pair >> 1) * KD + c * 8;
        } else {
            a_src[j] = Ah + (size_t)(v ? grow : row0) * KD + c * 8;
        }
        a_bytes[j] = v ? 16 : 0;
    }
    const __half* wbase = Wh + (size_t)e * KD * ND + n0;

    auto load_stage = [&](int s, int kt) {
        int k0 = kt * 64;
        uint32_t base = smb + s * 32768;
#pragma unroll
        for (int j = 0; j < 8; j++) {
            int idx = tid + 128 * j;
            int row = idx >> 3, c = idx & 7;
            uint32_t off = (uint32_t)row * 128 + (uint32_t)((c ^ (row & 7)) << 4);
            cp16(base + off, a_src[j] + k0, a_bytes[j]);
        }
#pragma unroll
        for (int j = 0; j < 8; j++) {
            int idx = tid + 128 * j;
            int k = idx >> 4, c = idx & 15;
            uint32_t off = 16384u + (uint32_t)k * 256 + (uint32_t)((c ^ (k & 7)) << 4);
            cp16(base + off, wbase + (size_t)(k0 + k) * ND + c * 8, 16);
        }
        asm volatile("cp.async.commit_group;");
    };

    float acc[4][8][4];
#pragma unroll
    for (int mi = 0; mi < 4; mi++)
#pragma unroll
        for (int ni = 0; ni < 8; ni++)
#pragma unroll
            for (int d = 0; d < 4; d++) acc[mi][ni][d] = 0.0f;

    constexpr int KT = KD / 64;
    load_stage(0, 0);
    load_stage(1, 1);

    for (int kt = 0; kt < KT; kt++) {
        if (kt + 1 < KT) asm volatile("cp.async.wait_group 1;");
        else             asm volatile("cp.async.wait_group 0;");
        __syncthreads();
        if (kt + 2 < KT) load_stage((kt + 2) % 3, kt + 2);

        uint32_t abase = smb + (kt % 3) * 32768;
        uint32_t bbase = abase + 16384;
#pragma unroll
        for (int ks = 0; ks < 4; ks++) {
            uint32_t a[4][4];
#pragma unroll
            for (int mi = 0; mi < 4; mi++) {
                int row = wm * 64 + mi * 16 + l15;
                uint32_t addr = abase + (uint32_t)row * 128 +
                                (uint32_t)(((ks * 2 + hi) ^ (row & 7)) << 4);
                ldsm4(a[mi], addr);
            }
            uint32_t b[4][4];
#pragma unroll
            for (int np = 0; np < 4; np++) {
                int krow = ks * 16 + l15;
                int c = wn * 8 + np * 2 + hi;
                uint32_t addr = bbase + (uint32_t)krow * 256 +
                                (uint32_t)((c ^ (krow & 7)) << 4);
                ldsm4t(b[np], addr);
            }
#pragma unroll
            for (int mi = 0; mi < 4; mi++)
#pragma unroll
                for (int np = 0; np < 4; np++) {
                    mma_f16(acc[mi][np * 2 + 0], a[mi], b[np] + 0);
                    mma_f16(acc[mi][np * 2 + 1], a[mi], b[np] + 2);
                }
        }
    }

    // ---- epilogue ----
    int r4 = lane >> 2, c2 = (lane & 3) * 2;
#pragma unroll
    for (int mi = 0; mi < 4; mi++) {
#pragma unroll
        for (int h = 0; h < 2; h++) {
            int grow = row0 + wm * 64 + mi * 16 + r4 + h * 8;
            if (grow < seg1) {
                if (FFN1) {
                    __half* orow = g_hidh + (size_t)grow * ND;
#pragma unroll
                    for (int ni = 0; ni < 8; ni++) {
                        int col = n0 + wn * 64 + ni * 8 + c2;
                        float2 bv = *(const float2*)(bias + (size_t)e * ND + col);
                        float v0 = gelu_exact(acc[mi][ni][h * 2 + 0] + bv.x);
                        float v1 = gelu_exact(acc[mi][ni][h * 2 + 1] + bv.y);
                        *(__half2*)(orow + col) = __floats2half2_rn(v0, v1);
                    }
                } else {
                    int pair = g_list[grow];
                    float wgt = g_topk_w[pair];
                    float* orow = outp + (size_t)(pair >> 1) * ND;
#pragma unroll
                    for (int ni = 0; ni < 8; ni++) {
                        int col = n0 + wn * 64 + ni * 8 + c2;
                        float2 bv = *(const float2*)(bias + (size_t)e * ND + col);
                        float v0 = (acc[mi][ni][h * 2 + 0] + bv.x) * wgt;
                        float v1 = (acc[mi][ni][h * 2 + 1] + bv.y) * wgt;
                        atomicAdd(orow + col, v0);
                        atomicAdd(orow + col + 1, v1);
                    }
                }
            }
        }
    }
}

// ---------------- launch --------------------------------------------------------
extern "C" void kernel_launch(void* const* d_in, const int* in_sizes, int n_in,
                              void* d_out, int out_size) {
    const float* x  = (const float*)d_in[0];
    const float* rw = (const float*)d_in[1];
    const float* w1 = (const float*)d_in[2];
    const float* b1 = (const float*)d_in[3];
    const float* w2 = (const float*)d_in[4];
    const float* b2 = (const float*)d_in[5];
    float* out = (float*)d_out;

    __half* xh;  cudaGetSymbolAddress((void**)&xh,  g_xh);
    __half* w1h; cudaGetSymbolAddress((void**)&w1h, g_w1h);
    __half* w2h; cudaGetSymbolAddress((void**)&w2h, g_w2h);
    __half* hid; cudaGetSymbolAddress((void**)&hid, g_hidh);

    constexpr int SMEM_BYTES = 3 * 32768;  // 98304
    cudaFuncSetAttribute(moe_gemm_h<HDIM, FDIM, true >,
                         cudaFuncAttributeMaxDynamicSharedMemorySize, SMEM_BYTES);
    cudaFuncSetAttribute(moe_gemm_h<FDIM, HDIM, false>,
                         cudaFuncAttributeMaxDynamicSharedMemorySize, SMEM_BYTES);

    // Lazily-created side stream + events (host handles only; reused so the
    // captured work is identical on every call).
    static cudaStream_t s2 = nullptr;
    static cudaEvent_t  ev_fork = nullptr, ev_w1 = nullptr, ev_w2 = nullptr;
    static cudaEvent_t  ev_sc = nullptr, ev_join = nullptr;
    if (s2 == nullptr) {
        cudaStreamCreateWithFlags(&s2, cudaStreamNonBlocking);
        cudaEventCreateWithFlags(&ev_fork, cudaEventDisableTiming);
        cudaEventCreateWithFlags(&ev_w1,   cudaEventDisableTiming);
        cudaEventCreateWithFlags(&ev_w2,   cudaEventDisableTiming);
        cudaEventCreateWithFlags(&ev_sc,   cudaEventDisableTiming);
        cudaEventCreateWithFlags(&ev_join, cudaEventDisableTiming);
    }

    size_t nw1  = (size_t)NE * HDIM * FDIM / 8;          // in float8 units
    size_t nw1h = nw1 / 2;                                // experts 0..3
    size_t ow1  = (size_t)4 * HDIM * FDIM;                // element offset e4
    size_t nw2  = (size_t)NE * FDIM * HDIM / 8;
    size_t no4  = (size_t)TOK * HDIM / 4;

    cudaEventRecord(ev_fork, 0);

    // ---- s2 (single side stream, R13-optimal priority order):
    //      cvt(w1 e0..3) [ev_w1] -> cvt(w1 e4..7) -> zero_out -> cvt(w2) [ev_w2]
    cudaStreamWaitEvent(s2, ev_fork, 0);
    cvt_half_kernel<<<(int)((nw1h + 255) / 256), 256, 0, s2>>>(w1, w1h, nw1h);
    cudaEventRecord(ev_w1, s2);
    cvt_half_kernel<<<(int)((nw1h + 255) / 256), 256, 0, s2>>>(w1 + ow1, w1h + ow1, nw1h);
    zero_out_kernel<<<(int)((no4 + 255) / 256), 256, 0, s2>>>(out, no4);
    cvt_half_kernel<<<(int)((nw2 + 255) / 256), 256, 0, s2>>>(w2, w2h, nw2);
    cudaEventRecord(ev_w2, s2);

    // ---- main stream: router (with fused x->fp16) chain ----
    router_kernel<<<TOK / 8, 256>>>(x, rw);
    scan_kernel<<<1, 32>>>();
    scatter_kernel<<<TOK / 256, 256>>>();
    cudaEventRecord(ev_sc, 0);   // implies xh fully written (router precedes)

    // ---- 2-way expert-group pipeline (R12 winner) ----
    cudaStreamWaitEvent(0, ev_w1, 0);             // w1h(e0..3); xh in-order on s0
    moe_gemm_h<HDIM, FDIM, true ><<<dim3(FDIM / 128, 4 * 64), 128, SMEM_BYTES>>>(
        xh, w1h, b1, out, 0);
    cudaStreamWaitEvent(s2, ev_sc, 0);            // router outputs + xh for FFN1b
    moe_gemm_h<HDIM, FDIM, true ><<<dim3(FDIM / 128, 4 * 64), 128, SMEM_BYTES, s2>>>(
        xh, w1h, b1, out, 4);

    cudaStreamWaitEvent(0, ev_w2, 0);             // w2h + zeroed out for FFN2a
    moe_gemm_h<FDIM, HDIM, false><<<dim3(HDIM / 128, 4 * 64), 128, SMEM_BYTES>>>(
        hid, w2h, b2, out, 0);
    moe_gemm_h<FDIM, HDIM, false><<<dim3(HDIM / 128, 4 * 64), 128, SMEM_BYTES, s2>>>(
        hid, w2h, b2, out, 4);

    // join side stream back to origin
    cudaEventRecord(ev_join, s2);
    cudaStreamWaitEvent(0, ev_join, 0);
}

// round 16
// speedup vs baseline: 1.0146x; 1.0056x over previous
#include <cuda_runtime.h>
#include <cuda_fp16.h>
#include <cstdint>

#define TOK   8192
#define HDIM  1024
#define FDIM  4096
#define NE    8

// ---------------- scratch (static device globals) ---------------------------
// g_counts / g_done are zero-initialized at module load; the router's last
// block re-zeroes them after use, so the invariant holds on every execution.
__device__ int    g_counts[NE];
__device__ int    g_done;
__device__ int    g_offsets[NE + 1];
__device__ int    g_cursor[NE];
__device__ int    g_topk_i[TOK * 2];
__device__ float  g_topk_w[TOK * 2];
__device__ int    g_list[TOK * 2];
__device__ __half g_xh[(size_t)TOK * HDIM];            // x in fp16 (written by router)
__device__ __half g_w1h[(size_t)NE * HDIM * FDIM];     // w1 in fp16
__device__ __half g_w2h[(size_t)NE * FDIM * HDIM];     // w2 in fp16
__device__ __half g_hidh[(size_t)TOK * 2 * FDIM];      // gelu(x@w1+b1) fp16

// ---------------- PTX helpers ------------------------------------------------
__device__ __forceinline__ uint32_t smem_u32(const void* p) {
    uint32_t a;
    asm("{ .reg .u64 t; cvta.to.shared.u64 t, %1; cvt.u32.u64 %0, t; }" : "=r"(a) : "l"(p));
    return a;
}
__device__ __forceinline__ void cp16(uint32_t dst, const void* src, int bytes) {
    asm volatile("cp.async.cg.shared.global [%0], [%1], 16, %2;"
                 :: "r"(dst), "l"(src), "r"(bytes));
}
__device__ __forceinline__ void ldsm4(uint32_t* r, uint32_t addr) {
    asm volatile("ldmatrix.sync.aligned.m8n8.x4.shared.b16 {%0,%1,%2,%3}, [%4];"
                 : "=r"(r[0]), "=r"(r[1]), "=r"(r[2]), "=r"(r[3]) : "r"(addr));
}
__device__ __forceinline__ void ldsm4t(uint32_t* r, uint32_t addr) {
    asm volatile("ldmatrix.sync.aligned.m8n8.x4.trans.shared.b16 {%0,%1,%2,%3}, [%4];"
                 : "=r"(r[0]), "=r"(r[1]), "=r"(r[2]), "=r"(r[3]) : "r"(addr));
}
__device__ __forceinline__ void mma_f16(float* d, const uint32_t* a, const uint32_t* b) {
    asm volatile(
        "mma.sync.aligned.m16n8k16.row.col.f32.f16.f16.f32 "
        "{%0,%1,%2,%3}, {%4,%5,%6,%7}, {%8,%9}, {%0,%1,%2,%3};"
        : "+f"(d[0]), "+f"(d[1]), "+f"(d[2]), "+f"(d[3])
        : "r"(a[0]), "r"(a[1]), "r"(a[2]), "r"(a[3]), "r"(b[0]), "r"(b[1]));
}
__device__ __forceinline__ float gelu_exact(float v) {
    return 0.5f * v * (1.0f + erff(v * 0.70710678118654752f));
}

// ---------------- small kernels ----------------------------------------------
__global__ void zero_out_kernel(float* __restrict__ out, size_t n4) {
    size_t i = (size_t)blockIdx.x * blockDim.x + threadIdx.x;
    if (i < n4) ((float4*)out)[i] = make_float4(0.f, 0.f, 0.f, 0.f);
}

__global__ void cvt_half_kernel(const float* __restrict__ src, __half* __restrict__ dst,
                                size_t n8) {
    size_t i = (size_t)blockIdx.x * blockDim.x + threadIdx.x;
    if (i < n8) {
        float4 v0 = ((const float4*)src)[i * 2];
        float4 v1 = ((const float4*)src)[i * 2 + 1];
        __half2 h[4];
        h[0] = __floats2half2_rn(v0.x, v0.y);
        h[1] = __floats2half2_rn(v0.z, v0.w);
        h[2] = __floats2half2_rn(v1.x, v1.y);
        h[3] = __floats2half2_rn(v1.z, v1.w);
        ((uint4*)dst)[i] = *(uint4*)h;
    }
}

// router + fused x->fp16 conversion + last-block scan (standard
// threadfence + arrival-counter pattern; the final block computes offsets,
// arms cursors, and re-zeros counts/done for the next call/replay).
__global__ void router_kernel(const float* __restrict__ x, const float* __restrict__ rw) {
    __shared__ float srw[NE * HDIM];
    int tid = threadIdx.x;
    for (int i = tid; i < NE * HDIM; i += 256) srw[i] = rw[i];
    __syncthreads();
    int warp = tid >> 5, lane = tid & 31;
    int t = blockIdx.x * 8 + warp;
    if (t < TOK) {
        const float* xr = x + (size_t)t * HDIM;
        __half* xhr = g_xh + (size_t)t * HDIM;
        float acc[NE];
#pragma unroll
        for (int e = 0; e < NE; e++) acc[e] = 0.0f;
        for (int h = lane; h < HDIM; h += 32) {
            float xv = xr[h];
            xhr[h] = __float2half_rn(xv);          // fused conversion (coalesced)
#pragma unroll
            for (int e = 0; e < NE; e++) acc[e] += xv * srw[e * HDIM + h];
        }
#pragma unroll
        for (int off = 16; off > 0; off >>= 1)
#pragma unroll
            for (int e = 0; e < NE; e++) acc[e] += __shfl_xor_sync(0xffffffffu, acc[e], off);
        if (lane == 0) {
            float mx = acc[0];
#pragma unroll
            for (int e = 1; e < NE; e++) mx = fmaxf(mx, acc[e]);
            float p[NE], s = 0.0f;
#pragma unroll
            for (int e = 0; e < NE; e++) { p[e] = expf(acc[e] - mx); s += p[e]; }
            float inv = 1.0f / s;
#pragma unroll
            for (int e = 0; e < NE; e++) p[e] *= inv;
            int i1 = 0;
#pragma unroll
            for (int e = 1; e < NE; e++) if (p[e] > p[i1]) i1 = e;
            int i2 = (i1 == 0) ? 1 : 0;
#pragma unroll
            for (int e = 0; e < NE; e++) if (e != i1 && p[e] > p[i2]) i2 = e;
            g_topk_i[t * 2 + 0] = i1; g_topk_w[t * 2 + 0] = p[i1];
            g_topk_i[t * 2 + 1] = i2; g_topk_w[t * 2 + 1] = p[i2];
            atomicAdd(&g_counts[i1], 1);
            atomicAdd(&g_counts[i2], 1);
        }
    }
    // ---- last-block scan (replaces scan_kernel) ----
    __syncthreads();
    if (tid == 0) {
        __threadfence();                      // publish this block's atomics
        int prev = atomicAdd(&g_done, 1);
        if (prev == (int)gridDim.x - 1) {     // last block to arrive
            __threadfence();                  // observe all blocks' counts
            g_done = 0;                       // re-arm for next call/replay
            int o = 0;
            g_offsets[0] = 0;
            for (int e = 0; e < NE; e++) {
                g_cursor[e] = o;
                o += g_counts[e];
                g_offsets[e + 1] = o;
                g_counts[e] = 0;              // re-arm for next call/replay
            }
            __threadfence();                  // publish scan results
        }
    }
}

__global__ void scatter_kernel() {
    int t = blockIdx.x * 256 + threadIdx.x;
    if (t < TOK) {
#pragma unroll
        for (int s = 0; s < 2; s++) {
            int e = g_topk_i[t * 2 + s];
            int pos = atomicAdd(&g_cursor[e], 1);
            g_list[pos] = t * 2 + s;
        }
    }
}

// ---------------- fp16 grouped GEMM (m16n8k16 + ldmatrix) --------------------
// Tile 128x128, BK=64, 128 threads = 4 warps (2Mx2N), warp tile 64x64.
// 3-stage cp.async pipeline, one __syncthreads per K-tile. (R4 hot loop.)
// Covers a 4-expert group starting at e0 (blockIdx.y: 4 experts x 64 rowtiles).
template <int KD, int ND, bool FFN1>
__global__ void __launch_bounds__(128, 2)
moe_gemm_h(const __half* __restrict__ Ah, const __half* __restrict__ Wh,
           const float* __restrict__ bias, float* __restrict__ outp, int e0) {
    extern __shared__ char smem[];
    uint32_t smb = smem_u32(smem);

    int tid = threadIdx.x;
    int warp = tid >> 5, lane = tid & 31;
    int wm = warp & 1, wn = warp >> 1;
    int l15 = lane & 15, hi = lane >> 4;

    int e = e0 + (blockIdx.y >> 6);
    int rt = blockIdx.y & 63;
    int seg0 = g_offsets[e], seg1 = g_offsets[e + 1];
    int row0 = seg0 + rt * 128;
    if (row0 >= seg1) return;
    int n0 = blockIdx.x * 128;

    // ---- A loader: 8 chunks/thread ----
    const __half* a_src[8];
    int a_bytes[8];
#pragma unroll
    for (int j = 0; j < 8; j++) {
        int idx = tid + 128 * j;
        int row = idx >> 3, c = idx & 7;
        int grow = row0 + row;
        bool v = grow < seg1;
        if (FFN1) {
            int pair = v ? g_list[grow] : 0;
            a_src[j] = Ah + (size_t)(pair >> 1) * KD + c * 8;
        } else {
            a_src[j] = Ah + (size_t)(v ? grow : row0) * KD + c * 8;
        }
        a_bytes[j] = v ? 16 : 0;
    }
    const __half* wbase = Wh + (size_t)e * KD * ND + n0;

    auto load_stage = [&](int s, int kt) {
        int k0 = kt * 64;
        uint32_t base = smb + s * 32768;
#pragma unroll
        for (int j = 0; j < 8; j++) {
            int idx = tid + 128 * j;
            int row = idx >> 3, c = idx & 7;
            uint32_t off = (uint32_t)row * 128 + (uint32_t)((c ^ (row & 7)) << 4);
            cp16(base + off, a_src[j] + k0, a_bytes[j]);
        }
#pragma unroll
        for (int j = 0; j < 8; j++) {
            int idx = tid + 128 * j;
            int k = idx >> 4, c = idx & 15;
            uint32_t off = 16384u + (uint32_t)k * 256 + (uint32_t)((c ^ (k & 7)) << 4);
            cp16(base + off, wbase + (size_t)(k0 + k) * ND + c * 8, 16);
        }
        asm volatile("cp.async.commit_group;");
    };

    float acc[4][8][4];
#pragma unroll
    for (int mi = 0; mi < 4; mi++)
#pragma unroll
        for (int ni = 0; ni < 8; ni++)
#pragma unroll
            for (int d = 0; d < 4; d++) acc[mi][ni][d] = 0.0f;

    constexpr int KT = KD / 64;
    load_stage(0, 0);
    load_stage(1, 1);

    for (int kt = 0; kt < KT; kt++) {
        if (kt + 1 < KT) asm volatile("cp.async.wait_group 1;");
        else             asm volatile("cp.async.wait_group 0;");
        __syncthreads();
        if (kt + 2 < KT) load_stage((kt + 2) % 3, kt + 2);

        uint32_t abase = smb + (kt % 3) * 32768;
        uint32_t bbase = abase + 16384;
#pragma unroll
        for (int ks = 0; ks < 4; ks++) {
            uint32_t a[4][4];
#pragma unroll
            for (int mi = 0; mi < 4; mi++) {
                int row = wm * 64 + mi * 16 + l15;
                uint32_t addr = abase + (uint32_t)row * 128 +
                                (uint32_t)(((ks * 2 + hi) ^ (row & 7)) << 4);
                ldsm4(a[mi], addr);
            }
            uint32_t b[4][4];
#pragma unroll
            for (int np = 0; np < 4; np++) {
                int krow = ks * 16 + l15;
                int c = wn * 8 + np * 2 + hi;
                uint32_t addr = bbase + (uint32_t)krow * 256 +
                                (uint32_t)((c ^ (krow & 7)) << 4);
                ldsm4t(b[np], addr);
            }
#pragma unroll
            for (int mi = 0; mi < 4; mi++)
#pragma unroll
                for (int np = 0; np < 4; np++) {
                    mma_f16(acc[mi][np * 2 + 0], a[mi], b[np] + 0);
                    mma_f16(acc[mi][np * 2 + 1], a[mi], b[np] + 2);
                }
        }
    }

    // ---- epilogue ----
    int r4 = lane >> 2, c2 = (lane & 3) * 2;
#pragma unroll
    for (int mi = 0; mi < 4; mi++) {
#pragma unroll
        for (int h = 0; h < 2; h++) {
            int grow = row0 + wm * 64 + mi * 16 + r4 + h * 8;
            if (grow < seg1) {
                if (FFN1) {
                    __half* orow = g_hidh + (size_t)grow * ND;
#pragma unroll
                    for (int ni = 0; ni < 8; ni++) {
                        int col = n0 + wn * 64 + ni * 8 + c2;
                        float2 bv = *(const float2*)(bias + (size_t)e * ND + col);
                        float v0 = gelu_exact(acc[mi][ni][h * 2 + 0] + bv.x);
                        float v1 = gelu_exact(acc[mi][ni][h * 2 + 1] + bv.y);
                        *(__half2*)(orow + col) = __floats2half2_rn(v0, v1);
                    }
                } else {
                    int pair = g_list[grow];
                    float wgt = g_topk_w[pair];
                    float* orow = outp + (size_t)(pair >> 1) * ND;
#pragma unroll
                    for (int ni = 0; ni < 8; ni++) {
                        int col = n0 + wn * 64 + ni * 8 + c2;
                        float2 bv = *(const float2*)(bias + (size_t)e * ND + col);
                        float v0 = (acc[mi][ni][h * 2 + 0] + bv.x) * wgt;
                        float v1 = (acc[mi][ni][h * 2 + 1] + bv.y) * wgt;
                        atomicAdd(orow + col, v0);
                        atomicAdd(orow + col + 1, v1);
                    }
                }
            }
        }
    }
}

// ---------------- launch --------------------------------------------------------
extern "C" void kernel_launch(void* const* d_in, const int* in_sizes, int n_in,
                              void* d_out, int out_size) {
    const float* x  = (const float*)d_in[0];
    const float* rw = (const float*)d_in[1];
    const float* w1 = (const float*)d_in[2];
    const float* b1 = (const float*)d_in[3];
    const float* w2 = (const float*)d_in[4];
    const float* b2 = (const float*)d_in[5];
    float* out = (float*)d_out;

    __half* xh;  cudaGetSymbolAddress((void**)&xh,  g_xh);
    __half* w1h; cudaGetSymbolAddress((void**)&w1h, g_w1h);
    __half* w2h; cudaGetSymbolAddress((void**)&w2h, g_w2h);
    __half* hid; cudaGetSymbolAddress((void**)&hid, g_hidh);

    constexpr int SMEM_BYTES = 3 * 32768;  // 98304
    cudaFuncSetAttribute(moe_gemm_h<HDIM, FDIM, true >,
                         cudaFuncAttributeMaxDynamicSharedMemorySize, SMEM_BYTES);
    cudaFuncSetAttribute(moe_gemm_h<FDIM, HDIM, false>,
                         cudaFuncAttributeMaxDynamicSharedMemorySize, SMEM_BYTES);

    // Lazily-created side stream + events (host handles only; reused so the
    // captured work is identical on every call).
    static cudaStream_t s2 = nullptr;
    static cudaEvent_t  ev_fork = nullptr, ev_w1 = nullptr, ev_w2 = nullptr;
    static cudaEvent_t  ev_sc = nullptr, ev_join = nullptr;
    if (s2 == nullptr) {
        cudaStreamCreateWithFlags(&s2, cudaStreamNonBlocking);
        cudaEventCreateWithFlags(&ev_fork, cudaEventDisableTiming);
        cudaEventCreateWithFlags(&ev_w1,   cudaEventDisableTiming);
        cudaEventCreateWithFlags(&ev_w2,   cudaEventDisableTiming);
        cudaEventCreateWithFlags(&ev_sc,   cudaEventDisableTiming);
        cudaEventCreateWithFlags(&ev_join, cudaEventDisableTiming);
    }

    size_t nw1  = (size_t)NE * HDIM * FDIM / 8;          // in float8 units
    size_t nw1h = nw1 / 2;                                // experts 0..3
    size_t ow1  = (size_t)4 * HDIM * FDIM;                // element offset e4
    size_t nw2  = (size_t)NE * FDIM * HDIM / 8;
    size_t no4  = (size_t)TOK * HDIM / 4;

    cudaEventRecord(ev_fork, 0);

    // ---- s2 (single side stream, priority order):
    //      cvt(w1 e0..3) [ev_w1] -> cvt(w1 e4..7) -> zero_out -> cvt(w2) [ev_w2]
    cudaStreamWaitEvent(s2, ev_fork, 0);
    cvt_half_kernel<<<(int)((nw1h + 255) / 256), 256, 0, s2>>>(w1, w1h, nw1h);
    cudaEventRecord(ev_w1, s2);
    cvt_half_kernel<<<(int)((nw1h + 255) / 256), 256, 0, s2>>>(w1 + ow1, w1h + ow1, nw1h);
    zero_out_kernel<<<(int)((no4 + 255) / 256), 256, 0, s2>>>(out, no4);
    cvt_half_kernel<<<(int)((nw2 + 255) / 256), 256, 0, s2>>>(w2, w2h, nw2);
    cudaEventRecord(ev_w2, s2);

    // ---- main stream: router (fused x->fp16 + last-block scan) -> scatter ----
    router_kernel<<<TOK / 8, 256>>>(x, rw);
    scatter_kernel<<<TOK / 256, 256>>>();
    cudaEventRecord(ev_sc, 0);   // implies xh + offsets + list fully written

    // ---- 2-way expert-group pipeline (R12 winner) ----
    cudaStreamWaitEvent(0, ev_w1, 0);             // w1h(e0..3); xh in-order on s0
    moe_gemm_h<HDIM, FDIM, true ><<<dim3(FDIM / 128, 4 * 64), 128, SMEM_BYTES>>>(
        xh, w1h, b1, out, 0);
    cudaStreamWaitEvent(s2, ev_sc, 0);            // router outputs + xh for FFN1b
    moe_gemm_h<HDIM, FDIM, true ><<<dim3(FDIM / 128, 4 * 64), 128, SMEM_BYTES, s2>>>(
        xh, w1h, b1, out, 4);

    cudaStreamWaitEvent(0, ev_w2, 0);             // w2h + zeroed out for FFN2a
    moe_gemm_h<FDIM, HDIM, false><<<dim3(HDIM / 128, 4 * 64), 128, SMEM_BYTES>>>(
        hid, w2h, b2, out, 0);
    moe_gemm_h<FDIM, HDIM, false><<<dim3(HDIM / 128, 4 * 64), 128, SMEM_BYTES, s2>>>(
        hid, w2h, b2, out, 4);

    // join side stream back to origin
    cudaEventRecord(ev_join, s2);
    cudaStreamWaitEvent(0, ev_join, 0);
}